// round 6
// baseline (speedup 1.0000x reference)
#include <cuda_runtime.h>
#include <cuda_fp16.h>

// Capsule routing, B=32, I=1024, O=64, D_in=16, D_out=32.
// R5: best-of recombination. Route = R2's G_=1 low-reg form (80 regs).
//     uhat = R3's 4-od-row FFMA2 form, split into 6 launches so ncu's
//     (-s 5 -c 1) window captures a uhat slice. squash takes n_parts.

#define B_   32
#define I_   1024
#define O_   64
#define DN   16
#define DD   32
#define OD   2048      // O_*DD
#define CH   8         // capsules (i) per route chunk
#define NCH  128       // I_/CH  (route partial granularity)
#define NS0  32        // sum0 partial granularity
#define OD4  512

__device__ __half g_uhat[(size_t)B_ * I_ * OD];  // 134 MB (fp16)
__device__ float  g_part[(size_t)NCH * B_ * OD]; // 33.5 MB partials (max gran)
__device__ float  g_bij [(size_t)B_ * I_ * O_];  // 8 MB routing logits
__device__ float  g_v   [(size_t)B_ * OD];       // v_j

#define FFMA2(d, a, b, c) \
    asm("fma.rn.f32x2 %0, %1, %2, %3;" : "=l"(d) : "l"(a), "l"(b), "l"(c))
#define MUL2(d, a, b) \
    asm("mul.rn.f32x2 %0, %1, %2;" : "=l"(d) : "l"(a), "l"(b))
#define PACK2(d, lo, hi) \
    asm("mov.b64 %0, {%1, %2};" : "=l"(d) : "f"(lo), "f"(hi))
#define UNPACK2(lo, hi, v) \
    asm("mov.b64 {%0, %1}, %2;" : "=f"(lo), "=f"(hi) : "l"(v))

// ---------------------------------------------------------------------------
// K1: u_hat (fp16). grid = (2 od-slices, nchunks), 256 threads.
// Thread owns 4 od rows; k paired into f32x2 lanes. 6 chunk-sliced launches.
// ---------------------------------------------------------------------------
__global__ __launch_bounds__(256, 2) void k_uhat(const float* __restrict__ x,
                                                 const float* __restrict__ W,
                                                 int chunk_base) {
    __shared__ float xs[CH][B_][DN];   // 16 KB
    const int od0 = blockIdx.x * 1024 + threadIdx.x * 4;
    const int i0  = (chunk_base + blockIdx.y) * CH;

    for (int j = threadIdx.x; j < CH * B_ * DN; j += 256) {
        int b  = j >> 7;
        int il = (j >> 4) & (CH - 1);
        int n  = j & (DN - 1);
        xs[il][b][n] = x[(size_t)b * (I_ * DN) + (i0 + il) * DN + n];
    }
    __syncthreads();

#pragma unroll 1
    for (int il = 0; il < CH; il++) {
        const int i = i0 + il;
        const float4* wr = reinterpret_cast<const float4*>(
            W + ((size_t)i * OD + od0) * DN);
        unsigned long long wp[32];          // [od][kpair] : od*8 + kp
#pragma unroll
        for (int r = 0; r < 16; r++) {
            const float4 f = wr[r];
            PACK2(wp[r * 2 + 0], f.x, f.y);
            PACK2(wp[r * 2 + 1], f.z, f.w);
        }
        __half* ubase = g_uhat + (size_t)i * OD + od0;

#pragma unroll 4
        for (int b = 0; b < B_; b++) {
            const float4* xb = reinterpret_cast<const float4*>(xs[il][b]);
            const float4 x0 = xb[0], x1 = xb[1], x2 = xb[2], x3 = xb[3];
            unsigned long long xp[8];
            PACK2(xp[0], x0.x, x0.y); PACK2(xp[1], x0.z, x0.w);
            PACK2(xp[2], x1.x, x1.y); PACK2(xp[3], x1.z, x1.w);
            PACK2(xp[4], x2.x, x2.y); PACK2(xp[5], x2.z, x2.w);
            PACK2(xp[6], x3.x, x3.y); PACK2(xp[7], x3.z, x3.w);

            unsigned long long acc[4];
#pragma unroll
            for (int od = 0; od < 4; od++) MUL2(acc[od], wp[od * 8], xp[0]);
#pragma unroll
            for (int kp = 1; kp < 8; kp++)
#pragma unroll
                for (int od = 0; od < 4; od++)
                    FFMA2(acc[od], wp[od * 8 + kp], xp[kp], acc[od]);

            float u[4];
#pragma unroll
            for (int od = 0; od < 4; od++) {
                float lo, hi;
                UNPACK2(lo, hi, acc[od]);
                u[od] = lo + hi;
            }
            const __half2 h01 = __floats2half2_rn(u[0], u[1]);
            const __half2 h23 = __floats2half2_rn(u[2], u[3]);
            uint2 st;
            st.x = *reinterpret_cast<const unsigned*>(&h01);
            st.y = *reinterpret_cast<const unsigned*>(&h23);
            *reinterpret_cast<uint2*>(ubase + (size_t)b * (I_ * OD)) = st;
        }
    }
}

// ---------------------------------------------------------------------------
// K1b: s0 partials (uniform c). grid = (NS0, 32); thread sums 32 i's.
// ---------------------------------------------------------------------------
__global__ __launch_bounds__(256) void k_sum0() {
    const int b = blockIdx.y;
    const int i0 = blockIdx.x * (I_ / NS0);
    const uint4* src = reinterpret_cast<const uint4*>(
        g_uhat + ((size_t)b * I_ + i0) * OD) + threadIdx.x;

    float4 r0 = {0,0,0,0}, r1 = {0,0,0,0};
#pragma unroll
    for (int il = 0; il < I_ / NS0; il++) {
        const uint4 u = src[il * 256];
        const __half2* h = reinterpret_cast<const __half2*>(&u);
        const float2 f0 = __half22float2(h[0]), f1 = __half22float2(h[1]);
        const float2 f2 = __half22float2(h[2]), f3 = __half22float2(h[3]);
        r0.x += f0.x; r0.y += f0.y; r0.z += f1.x; r0.w += f1.y;
        r1.x += f2.x; r1.y += f2.y; r1.z += f3.x; r1.w += f3.y;
    }
    float4* gp = reinterpret_cast<float4*>(
        g_part + ((size_t)blockIdx.x * B_ + b) * OD) + threadIdx.x * 2;
    gp[0] = r0;
    gp[1] = r1;
}

// ---------------------------------------------------------------------------
// K2: n_parts-reduce + squash. grid = (4, 32), 128 threads.
// ---------------------------------------------------------------------------
__global__ __launch_bounds__(128) void k_squash(int n_parts, float factor,
                                                const float* __restrict__ bias,
                                                float* __restrict__ out) {
    const int b    = blockIdx.y;
    const int w    = threadIdx.x >> 5;
    const int lane = threadIdx.x & 31;
    const int o    = blockIdx.x * 16 + w * 4 + (lane >> 3);
    const int dg   = lane & 7;

    const float4* gp = reinterpret_cast<const float4*>(g_part);
    const size_t base = (size_t)b * OD4 + o * 8 + dg;

    float4 a0 = {0,0,0,0}, a1 = {0,0,0,0}, a2 = {0,0,0,0}, a3 = {0,0,0,0};
#pragma unroll 4
    for (int t = 0; t < n_parts; t += 4) {
        float4 p0 = gp[(size_t)(t + 0) * B_ * OD4 + base];
        float4 p1 = gp[(size_t)(t + 1) * B_ * OD4 + base];
        float4 p2 = gp[(size_t)(t + 2) * B_ * OD4 + base];
        float4 p3 = gp[(size_t)(t + 3) * B_ * OD4 + base];
        a0.x += p0.x; a0.y += p0.y; a0.z += p0.z; a0.w += p0.w;
        a1.x += p1.x; a1.y += p1.y; a1.z += p1.z; a1.w += p1.w;
        a2.x += p2.x; a2.y += p2.y; a2.z += p2.z; a2.w += p2.w;
        a3.x += p3.x; a3.y += p3.y; a3.z += p3.z; a3.w += p3.w;
    }
    float4 s;
    s.x = (a0.x + a1.x + a2.x + a3.x) * factor;
    s.y = (a0.y + a1.y + a2.y + a3.y) * factor;
    s.z = (a0.z + a1.z + a2.z + a3.z) * factor;
    s.w = (a0.w + a1.w + a2.w + a3.w) * factor;
    if (bias) {
        const float4 bb = reinterpret_cast<const float4*>(bias)[o * 8 + dg];
        s.x += bb.x; s.y += bb.y; s.z += bb.z; s.w += bb.w;
    }

    float q = s.x * s.x + s.y * s.y + s.z * s.z + s.w * s.w;
    q += __shfl_xor_sync(0xffffffffu, q, 1);
    q += __shfl_xor_sync(0xffffffffu, q, 2);
    q += __shfl_xor_sync(0xffffffffu, q, 4);

    const float scale = q / (1.f + q) * rsqrtf(q + 1e-8f);
    s.x *= scale; s.y *= scale; s.z *= scale; s.w *= scale;
    float4* dst = reinterpret_cast<float4*>(out ? out : g_v);
    dst[(size_t)b * OD4 + o * 8 + dg] = s;
}

// ---------------------------------------------------------------------------
// K3: one routing pass, register-resident (R2 form, 80 regs).
// grid = (128 chunks, 32 batches), 256 threads.
// ---------------------------------------------------------------------------
__global__ __launch_bounds__(256) void k_route(int use_bij_in, int write_bij) {
    __shared__ float sa[CH][O_];
    __shared__ float sc[CH][O_];

    const int b  = blockIdx.y;
    const int i0 = blockIdx.x * CH;
    const int t  = threadIdx.x;
    const int o  = t >> 2;

    const uint4* usrc = reinterpret_cast<const uint4*>(
        g_uhat + ((size_t)b * I_ + i0) * OD) + t;
    uint4 u[CH];
#pragma unroll
    for (int il = 0; il < CH; il++) u[il] = usrc[il * 256];

    const float4* vsrc =
        reinterpret_cast<const float4*>(g_v + (size_t)b * OD) + t * 2;
    const float4 v0 = vsrc[0], v1 = vsrc[1];

#pragma unroll
    for (int il = 0; il < CH; il++) {
        const __half2* h = reinterpret_cast<const __half2*>(&u[il]);
        const float2 f0 = __half22float2(h[0]), f1 = __half22float2(h[1]);
        const float2 f2 = __half22float2(h[2]), f3 = __half22float2(h[3]);
        float a;
        a  = f0.x * v0.x;         a = fmaf(f0.y, v0.y, a);
        a  = fmaf(f1.x, v0.z, a); a = fmaf(f1.y, v0.w, a);
        a  = fmaf(f2.x, v1.x, a); a = fmaf(f2.y, v1.y, a);
        a  = fmaf(f3.x, v1.z, a); a = fmaf(f3.y, v1.w, a);
        a += __shfl_xor_sync(0xffffffffu, a, 1);
        a += __shfl_xor_sync(0xffffffffu, a, 2);
        if ((t & 3) == 0) sa[il][o] = a;
    }
    __syncthreads();

    {
        const int wid  = t >> 5;
        const int lane = t & 31;
        const int i = i0 + wid;
        float a0 = sa[wid][lane];
        float a1 = sa[wid][lane + 32];
        if (use_bij_in) {
            a0 += g_bij[((size_t)b * I_ + i) * O_ + lane];
            a1 += g_bij[((size_t)b * I_ + i) * O_ + lane + 32];
        }
        if (write_bij) {
            g_bij[((size_t)b * I_ + i) * O_ + lane]      = a0;
            g_bij[((size_t)b * I_ + i) * O_ + lane + 32] = a1;
        }
        float m = fmaxf(a0, a1);
#pragma unroll
        for (int s = 16; s > 0; s >>= 1)
            m = fmaxf(m, __shfl_xor_sync(0xffffffffu, m, s));
        const float e0 = __expf(a0 - m);
        const float e1 = __expf(a1 - m);
        float es = e0 + e1;
#pragma unroll
        for (int s = 16; s > 0; s >>= 1)
            es += __shfl_xor_sync(0xffffffffu, es, s);
        const float inv = 1.f / es;
        sc[wid][lane]      = e0 * inv;
        sc[wid][lane + 32] = e1 * inv;
    }
    __syncthreads();

    float4 r0 = {0,0,0,0}, r1 = {0,0,0,0};
#pragma unroll
    for (int il = 0; il < CH; il++) {
        const float s = sc[il][o];
        const __half2* h = reinterpret_cast<const __half2*>(&u[il]);
        const float2 f0 = __half22float2(h[0]), f1 = __half22float2(h[1]);
        const float2 f2 = __half22float2(h[2]), f3 = __half22float2(h[3]);
        r0.x = fmaf(s, f0.x, r0.x); r0.y = fmaf(s, f0.y, r0.y);
        r0.z = fmaf(s, f1.x, r0.z); r0.w = fmaf(s, f1.y, r0.w);
        r1.x = fmaf(s, f2.x, r1.x); r1.y = fmaf(s, f2.y, r1.y);
        r1.z = fmaf(s, f3.x, r1.z); r1.w = fmaf(s, f3.y, r1.w);
    }
    float4* gp = reinterpret_cast<float4*>(
        g_part + ((size_t)blockIdx.x * B_ + b) * OD) + t * 2;
    gp[0] = r0;
    gp[1] = r1;
}

// ---------------------------------------------------------------------------
extern "C" void kernel_launch(void* const* d_in, const int* in_sizes, int n_in,
                              void* d_out, int out_size) {
    const float* x    = (const float*)d_in[0];   // [32,1024,16]
    const float* W    = (const float*)d_in[1];   // [1,1024,64,32,16]
    const float* bias = (const float*)d_in[2];   // [1,1,64,32]
    float* out = (float*)d_out;                  // [32,64,32]

    // uhat split 6-way: 22+22+21+21+21+21 = 128 chunks.
    // Launch #6 is a uhat slice -> ncu (-s 5 -c 1) profiles k_uhat.
    k_uhat<<<dim3(2, 22), 256>>>(x, W, 0);                               // 1
    k_uhat<<<dim3(2, 22), 256>>>(x, W, 22);                              // 2
    k_uhat<<<dim3(2, 21), 256>>>(x, W, 44);                              // 3
    k_uhat<<<dim3(2, 21), 256>>>(x, W, 65);                              // 4
    k_uhat<<<dim3(2, 21), 256>>>(x, W, 86);                              // 5
    k_uhat<<<dim3(2, 21), 256>>>(x, W, 107);                             // 6 (ncu)
    k_sum0<<<dim3(NS0, B_), 256>>>();                                    // 7
    k_squash<<<dim3(4, 32), 128>>>(NS0, 1.0f / 64.0f, nullptr, nullptr); // v0
    k_route<<<dim3(NCH, B_), 256>>>(0, 1);
    k_squash<<<dim3(4, 32), 128>>>(NCH, 1.0f, nullptr, nullptr);         // v1
    k_route<<<dim3(NCH, B_), 256>>>(1, 0);
    k_squash<<<dim3(4, 32), 128>>>(NCH, 1.0f, bias, out);                // out
}

// round 7
// speedup vs baseline: 1.9152x; 1.9152x over previous
#include <cuda_runtime.h>
#include <cuda_fp16.h>

// Capsule routing, B=32, I=1024, O=64, D_in=16, D_out=32.
// R6: k_uhat is issue-bound (measured: active SMs at ~100% issue) -> remove
//     all PACK/UNPACK movs via register-pair aliasing (ulonglong2 loads),
//     128-thr blocks for wave balance. sum0+squash fused (k_s0squash).
//     Route = proven R2 form (30.2us).

#define B_   32
#define I_   1024
#define O_   64
#define DN   16
#define DD   32
#define OD   2048      // O_*DD
#define CH   8         // capsules (i) per route chunk
#define NCH  128       // I_/CH  (route partial granularity)
#define OD4  512

__device__ __half g_uhat[(size_t)B_ * I_ * OD];  // 134 MB (fp16)
__device__ float  g_part[(size_t)NCH * B_ * OD]; // 33.5 MB route partials
__device__ float  g_bij [(size_t)B_ * I_ * O_];  // 8 MB routing logits
__device__ float  g_v   [(size_t)B_ * OD];       // v_j

#define FFMA2(d, a, b, c) \
    asm("fma.rn.f32x2 %0, %1, %2, %3;" : "=l"(d) : "l"(a), "l"(b), "l"(c))
#define MUL2(d, a, b) \
    asm("mul.rn.f32x2 %0, %1, %2;" : "=l"(d) : "l"(a), "l"(b))

// ---------------------------------------------------------------------------
// K1: u_hat (fp16). grid = (4 od-slices, 128 chunks), 128 threads.
// Thread owns 4 od rows; k paired into f32x2 lanes. All pair operands come
// from 128-bit loads whose halves ARE aligned register pairs (no movs).
// ---------------------------------------------------------------------------
__global__ __launch_bounds__(128, 4) void k_uhat(const float* __restrict__ x,
                                                 const float* __restrict__ W) {
    __shared__ float xs[CH][B_][DN];   // 16 KB
    const int od0 = blockIdx.x * 512 + threadIdx.x * 4;
    const int i0  = blockIdx.y * CH;

    // cooperative vectorized load of x[:, i0:i0+8, :] (1024 float4)
#pragma unroll
    for (int k = 0; k < 8; k++) {
        const int j  = threadIdx.x + k * 128;
        const int b  = j >> 5;
        const int r  = j & 31;
        const int il = r >> 2;
        const int nq = r & 3;
        *reinterpret_cast<float4*>(&xs[il][b][nq * 4]) =
            *reinterpret_cast<const float4*>(
                x + (size_t)b * (I_ * DN) + (i0 + il) * DN + nq * 4);
    }
    __syncthreads();

#pragma unroll 1
    for (int il = 0; il < CH; il++) {
        const int i = i0 + il;
        const ulonglong2* wr = reinterpret_cast<const ulonglong2*>(
            W + ((size_t)i * OD + od0) * DN);
        unsigned long long wp[32];          // wp[od*8+kp]
#pragma unroll
        for (int r = 0; r < 16; r++) {
            const ulonglong2 lw = wr[r];
            wp[r * 2 + 0] = lw.x;
            wp[r * 2 + 1] = lw.y;
        }
        __half* ubase = g_uhat + (size_t)i * OD + od0;

#pragma unroll 4
        for (int b = 0; b < B_; b++) {
            const ulonglong2* xq =
                reinterpret_cast<const ulonglong2*>(xs[il][b]);
            unsigned long long xp[8];
#pragma unroll
            for (int r = 0; r < 4; r++) {
                const ulonglong2 lx = xq[r];
                xp[r * 2 + 0] = lx.x;
                xp[r * 2 + 1] = lx.y;
            }

            unsigned long long acc[4];
#pragma unroll
            for (int od = 0; od < 4; od++) MUL2(acc[od], wp[od * 8], xp[0]);
#pragma unroll
            for (int kp = 1; kp < 8; kp++)
#pragma unroll
                for (int od = 0; od < 4; od++)
                    FFMA2(acc[od], wp[od * 8 + kp], xp[kp], acc[od]);

            const float2 p0 = *reinterpret_cast<float2*>(&acc[0]);
            const float2 p1 = *reinterpret_cast<float2*>(&acc[1]);
            const float2 p2 = *reinterpret_cast<float2*>(&acc[2]);
            const float2 p3 = *reinterpret_cast<float2*>(&acc[3]);
            const __half2 h01 = __floats2half2_rn(p0.x + p0.y, p1.x + p1.y);
            const __half2 h23 = __floats2half2_rn(p2.x + p2.y, p3.x + p3.y);
            uint2 st;
            st.x = *reinterpret_cast<const unsigned*>(&h01);
            st.y = *reinterpret_cast<const unsigned*>(&h23);
            *reinterpret_cast<uint2*>(ubase + (size_t)b * (I_ * OD)) = st;
        }
    }
}

// ---------------------------------------------------------------------------
// K1b: fused s0 reduction + squash -> v0. grid = (16 o-slices, 32 b),
// 256 threads. Block: batch b, o's [4*bx, 4*bx+4), reduce all 1024 i.
// ---------------------------------------------------------------------------
__global__ __launch_bounds__(256) void k_s0squash() {
    __shared__ float red[16][128];   // 8 KB
    const int b  = blockIdx.y;
    const int o0 = blockIdx.x * 4;
    const int t  = threadIdx.x;
    const int tq = t & 15;           // od-quad within the 128-od slice
    const int ig = t >> 4;           // i-group (16 groups)

    const __half* base = g_uhat + (size_t)b * (I_ * OD) + o0 * DD + tq * 8;
    float r[8] = {0, 0, 0, 0, 0, 0, 0, 0};
#pragma unroll 4
    for (int i = ig; i < I_; i += 16) {
        const uint4 u = *reinterpret_cast<const uint4*>(base + (size_t)i * OD);
        const __half2* h = reinterpret_cast<const __half2*>(&u);
        const float2 f0 = __half22float2(h[0]), f1 = __half22float2(h[1]);
        const float2 f2 = __half22float2(h[2]), f3 = __half22float2(h[3]);
        r[0] += f0.x; r[1] += f0.y; r[2] += f1.x; r[3] += f1.y;
        r[4] += f2.x; r[5] += f2.y; r[6] += f3.x; r[7] += f3.y;
    }
#pragma unroll
    for (int k = 0; k < 8; k++) red[ig][tq * 8 + k] = r[k];
    __syncthreads();

    if (t < 128) {
        float s = 0.f;
#pragma unroll
        for (int g = 0; g < 16; g++) s += red[g][t];
        s *= (1.0f / 64.0f);

        float q = s * s;    // o = t>>5 (warp), d = t&31 (lane)
#pragma unroll
        for (int sh = 16; sh > 0; sh >>= 1)
            q += __shfl_xor_sync(0xffffffffu, q, sh);
        const float scale = q / (1.f + q) * rsqrtf(q + 1e-8f);
        g_v[(size_t)b * OD + o0 * DD + t] = scale * s;
    }
}

// ---------------------------------------------------------------------------
// K2: route-partial reduce + squash. grid = (4, 32), 128 threads.
// ---------------------------------------------------------------------------
__global__ __launch_bounds__(128) void k_squash(const float* __restrict__ bias,
                                                float* __restrict__ out) {
    const int b    = blockIdx.y;
    const int w    = threadIdx.x >> 5;
    const int lane = threadIdx.x & 31;
    const int o    = blockIdx.x * 16 + w * 4 + (lane >> 3);
    const int dg   = lane & 7;

    const float4* gp = reinterpret_cast<const float4*>(g_part);
    const size_t base = (size_t)b * OD4 + o * 8 + dg;

    float4 a0 = {0,0,0,0}, a1 = {0,0,0,0}, a2 = {0,0,0,0}, a3 = {0,0,0,0};
#pragma unroll 4
    for (int t = 0; t < NCH; t += 4) {
        float4 p0 = gp[(size_t)(t + 0) * B_ * OD4 + base];
        float4 p1 = gp[(size_t)(t + 1) * B_ * OD4 + base];
        float4 p2 = gp[(size_t)(t + 2) * B_ * OD4 + base];
        float4 p3 = gp[(size_t)(t + 3) * B_ * OD4 + base];
        a0.x += p0.x; a0.y += p0.y; a0.z += p0.z; a0.w += p0.w;
        a1.x += p1.x; a1.y += p1.y; a1.z += p1.z; a1.w += p1.w;
        a2.x += p2.x; a2.y += p2.y; a2.z += p2.z; a2.w += p2.w;
        a3.x += p3.x; a3.y += p3.y; a3.z += p3.z; a3.w += p3.w;
    }
    float4 s;
    s.x = a0.x + a1.x + a2.x + a3.x;
    s.y = a0.y + a1.y + a2.y + a3.y;
    s.z = a0.z + a1.z + a2.z + a3.z;
    s.w = a0.w + a1.w + a2.w + a3.w;
    if (bias) {
        const float4 bb = reinterpret_cast<const float4*>(bias)[o * 8 + dg];
        s.x += bb.x; s.y += bb.y; s.z += bb.z; s.w += bb.w;
    }

    float q = s.x * s.x + s.y * s.y + s.z * s.z + s.w * s.w;
    q += __shfl_xor_sync(0xffffffffu, q, 1);
    q += __shfl_xor_sync(0xffffffffu, q, 2);
    q += __shfl_xor_sync(0xffffffffu, q, 4);

    const float scale = q / (1.f + q) * rsqrtf(q + 1e-8f);
    s.x *= scale; s.y *= scale; s.z *= scale; s.w *= scale;
    float4* dst = reinterpret_cast<float4*>(out ? out : g_v);
    dst[(size_t)b * OD4 + o * 8 + dg] = s;
}

// ---------------------------------------------------------------------------
// K3: one routing pass, register-resident (proven 80-reg form).
// grid = (128 chunks, 32 batches), 256 threads.
// ---------------------------------------------------------------------------
__global__ __launch_bounds__(256) void k_route(int use_bij_in, int write_bij) {
    __shared__ float sa[CH][O_];
    __shared__ float sc[CH][O_];

    const int b  = blockIdx.y;
    const int i0 = blockIdx.x * CH;
    const int t  = threadIdx.x;
    const int o  = t >> 2;

    const uint4* usrc = reinterpret_cast<const uint4*>(
        g_uhat + ((size_t)b * I_ + i0) * OD) + t;
    uint4 u[CH];
#pragma unroll
    for (int il = 0; il < CH; il++) u[il] = usrc[il * 256];

    const float4* vsrc =
        reinterpret_cast<const float4*>(g_v + (size_t)b * OD) + t * 2;
    const float4 v0 = vsrc[0], v1 = vsrc[1];

#pragma unroll
    for (int il = 0; il < CH; il++) {
        const __half2* h = reinterpret_cast<const __half2*>(&u[il]);
        const float2 f0 = __half22float2(h[0]), f1 = __half22float2(h[1]);
        const float2 f2 = __half22float2(h[2]), f3 = __half22float2(h[3]);
        float a;
        a  = f0.x * v0.x;         a = fmaf(f0.y, v0.y, a);
        a  = fmaf(f1.x, v0.z, a); a = fmaf(f1.y, v0.w, a);
        a  = fmaf(f2.x, v1.x, a); a = fmaf(f2.y, v1.y, a);
        a  = fmaf(f3.x, v1.z, a); a = fmaf(f3.y, v1.w, a);
        a += __shfl_xor_sync(0xffffffffu, a, 1);
        a += __shfl_xor_sync(0xffffffffu, a, 2);
        if ((t & 3) == 0) sa[il][o] = a;
    }
    __syncthreads();

    {
        const int wid  = t >> 5;
        const int lane = t & 31;
        const int i = i0 + wid;
        float a0 = sa[wid][lane];
        float a1 = sa[wid][lane + 32];
        if (use_bij_in) {
            a0 += g_bij[((size_t)b * I_ + i) * O_ + lane];
            a1 += g_bij[((size_t)b * I_ + i) * O_ + lane + 32];
        }
        if (write_bij) {
            g_bij[((size_t)b * I_ + i) * O_ + lane]      = a0;
            g_bij[((size_t)b * I_ + i) * O_ + lane + 32] = a1;
        }
        float m = fmaxf(a0, a1);
#pragma unroll
        for (int s = 16; s > 0; s >>= 1)
            m = fmaxf(m, __shfl_xor_sync(0xffffffffu, m, s));
        const float e0 = __expf(a0 - m);
        const float e1 = __expf(a1 - m);
        float es = e0 + e1;
#pragma unroll
        for (int s = 16; s > 0; s >>= 1)
            es += __shfl_xor_sync(0xffffffffu, es, s);
        const float inv = 1.f / es;
        sc[wid][lane]      = e0 * inv;
        sc[wid][lane + 32] = e1 * inv;
    }
    __syncthreads();

    float4 r0 = {0,0,0,0}, r1 = {0,0,0,0};
#pragma unroll
    for (int il = 0; il < CH; il++) {
        const float s = sc[il][o];
        const __half2* h = reinterpret_cast<const __half2*>(&u[il]);
        const float2 f0 = __half22float2(h[0]), f1 = __half22float2(h[1]);
        const float2 f2 = __half22float2(h[2]), f3 = __half22float2(h[3]);
        r0.x = fmaf(s, f0.x, r0.x); r0.y = fmaf(s, f0.y, r0.y);
        r0.z = fmaf(s, f1.x, r0.z); r0.w = fmaf(s, f1.y, r0.w);
        r1.x = fmaf(s, f2.x, r1.x); r1.y = fmaf(s, f2.y, r1.y);
        r1.z = fmaf(s, f3.x, r1.z); r1.w = fmaf(s, f3.y, r1.w);
    }
    float4* gp = reinterpret_cast<float4*>(
        g_part + ((size_t)blockIdx.x * B_ + b) * OD) + t * 2;
    gp[0] = r0;
    gp[1] = r1;
}

// ---------------------------------------------------------------------------
extern "C" void kernel_launch(void* const* d_in, const int* in_sizes, int n_in,
                              void* d_out, int out_size) {
    const float* x    = (const float*)d_in[0];   // [32,1024,16]
    const float* W    = (const float*)d_in[1];   // [1,1024,64,32,16]
    const float* bias = (const float*)d_in[2];   // [1,1,64,32]
    float* out = (float*)d_out;                  // [32,64,32]

    k_uhat<<<dim3(4, 128), 128>>>(x, W);             // 1
    k_s0squash<<<dim3(16, 32), 256>>>();             // 2: v0
    k_route<<<dim3(NCH, B_), 256>>>(0, 1);           // 3
    k_squash<<<dim3(4, 32), 128>>>(nullptr, nullptr);// 4: v1
    k_route<<<dim3(NCH, B_), 256>>>(1, 0);           // 5
    k_squash<<<dim3(4, 32), 128>>>(bias, out);       // 6: out
}